// round 16
// baseline (speedup 1.0000x reference)
#include <cuda_runtime.h>
#include <cstdint>

#define BATCH 2
#define SEQ   2048
#define EMB   128
#define NH    8
#define HD    16
#define NROWS (BATCH*SEQ)
#define KTILE 64
#define NKV   2
#define PREC  20
#define KPAD  16     // uint16 per K smem row (32B)
#define VPAD  80     // uint16 per V^t smem row (160B)

// Scratch
__device__ float g_Q[BATCH*NH*SEQ*HD];
__device__ float g_K[BATCH*NH*SEQ*HD];
__device__ float g_Vt[BATCH*NH*HD*SEQ];
// Compacted bf16 hi/lo K and V^t (fragment-permuted)
__device__ __align__(16) uint16_t g_Khi[BATCH*NH*SEQ*HD];
__device__ __align__(16) uint16_t g_Klo[BATCH*NH*SEQ*HD];
__device__ __align__(16) uint16_t g_Vthi[BATCH*NH*HD*SEQ];
__device__ __align__(16) uint16_t g_Vtlo[BATCH*NH*HD*SEQ];
// W^T bf16 hi/lo (fragment-permuted): [mat][n(128)][k(128)]
__device__ __align__(16) uint16_t g_Wthi[3*EMB*EMB];
__device__ __align__(16) uint16_t g_Wtlo[3*EMB*EMB];
// Mask compaction
__device__ int g_cidx[BATCH*SEQ];
__device__ int g_nkeys[BATCH];
// Partials: [bh][q][z][PREC]
__device__ float g_part[BATCH*NH*SEQ*NKV*PREC];

__device__ __forceinline__ float ex2f(float x){
    float y; asm("ex2.approx.ftz.f32 %0, %1;" : "=f"(y) : "f"(x)); return y;
}
__device__ __forceinline__ uint32_t bf2(float even, float odd){
    uint32_t r;
    asm("cvt.rn.bf16x2.f32 %0, %1, %2;" : "=r"(r) : "f"(odd), "f"(even));
    return r;
}
__device__ __forceinline__ float bflo(uint32_t r){ return __uint_as_float(r << 16); }
__device__ __forceinline__ float bfhi(uint32_t r){ return __uint_as_float(r & 0xFFFF0000u); }
__device__ __forceinline__ uint32_t bfr(float x){ return bf2(x, 0.f) & 0xFFFFu; }

// fragment permutation within a 16-element block (verified R10-R15)
__device__ __forceinline__ int permF(int i){
    return (i < 8) ? (4 * (i >> 1) + (i & 1))
                   : (4 * ((i - 8) >> 1) + 2 + (i & 1));
}

__device__ __forceinline__ void mma16816(float c[4], const uint32_t a[4], const uint32_t b[2]){
    asm volatile(
        "mma.sync.aligned.m16n8k16.row.col.f32.bf16.bf16.f32 "
        "{%0,%1,%2,%3}, {%4,%5,%6,%7}, {%8,%9}, {%0,%1,%2,%3};\n"
        : "+f"(c[0]), "+f"(c[1]), "+f"(c[2]), "+f"(c[3])
        : "r"(a[0]), "r"(a[1]), "r"(a[2]), "r"(a[3]), "r"(b[0]), "r"(b[1]));
}

// ---------------------------------------------------------------------------
// Kernel 0a: W^T bf16 hi/lo precompute. 3072 threads: (mat, n, seg of 16 k).
// Reads W[k][n] (coalesced across n), writes permuted row n.
// ---------------------------------------------------------------------------
__global__ __launch_bounds__(256) void wconv_kernel(
    const float* __restrict__ Wq, const float* __restrict__ Wk,
    const float* __restrict__ Wv)
{
    const int t = blockIdx.x * 256 + threadIdx.x;   // 0..3071
    const int mat = t >> 10;
    const int n   = t & 127;
    const int seg = (t >> 7) & 7;
    const float* __restrict__ W = (mat == 0) ? Wq : (mat == 1) ? Wk : Wv;

    float x[16];
    #pragma unroll
    for (int i = 0; i < 16; i++)
        x[i] = W[(seg * 16 + i) * EMB + n];

    union { uint16_t u16[16]; uint4 u4[2]; } hh, ll;
    #pragma unroll
    for (int i = 0; i < 16; i++) {
        const uint32_t hb = bfr(x[i]);
        const uint32_t lb = bfr(x[i] - __uint_as_float(hb << 16));
        const int p = permF(i);
        hh.u16[p] = (uint16_t)hb;
        ll.u16[p] = (uint16_t)lb;
    }
    const size_t base = (size_t)mat * EMB * EMB + (size_t)n * EMB + seg * 16;
    *(uint4*)&g_Wthi[base]     = hh.u4[0];
    *(uint4*)&g_Wthi[base + 8] = hh.u4[1];
    *(uint4*)&g_Wtlo[base]     = ll.u4[0];
    *(uint4*)&g_Wtlo[base + 8] = ll.u4[1];
}

// ---------------------------------------------------------------------------
// Kernel 0b: mask compaction (unchanged from R15).
// ---------------------------------------------------------------------------
__global__ __launch_bounds__(256) void mask_scan_kernel(const int* __restrict__ mask)
{
    __shared__ int warpsum[8];
    const int b = blockIdx.x;
    const int tid = threadIdx.x;
    const int lane = tid & 31, w = tid >> 5;

    int flags[8], cnt = 0;
    #pragma unroll
    for (int i = 0; i < 8; i++) {
        flags[i] = (mask[b * SEQ + tid * 8 + i] != 0);
        cnt += flags[i];
    }
    int scan = cnt;
    #pragma unroll
    for (int off = 1; off < 32; off <<= 1) {
        const int n = __shfl_up_sync(0xFFFFFFFFu, scan, off);
        if (lane >= off) scan += n;
    }
    if (lane == 31) warpsum[w] = scan;
    __syncthreads();
    int wbase = 0;
    #pragma unroll
    for (int i = 0; i < 8; i++)
        if (i < w) wbase += warpsum[i];
    int pos = wbase + scan - cnt;
    #pragma unroll
    for (int i = 0; i < 8; i++) {
        if (flags[i]) g_cidx[b * SEQ + pos++] = tid * 8 + i;
    }
    if (tid == 255) g_nkeys[b] = wbase + scan;
}

// ---------------------------------------------------------------------------
// Kernel 1: QKV projection on tensor cores (mma.sync, bf16 hi/lo 3-term).
// Grid (64 row-tiles, 3 mats, 4 n-quarters), 128 threads (4 warps).
// Warp = 16 X-rows; A-frags resident (8 ksteps hi/lo); 4 n-tiles x 24 mma.
// B-frags loaded directly from L2-resident g_Wt (same layout as attn K).
// ---------------------------------------------------------------------------
__global__ __launch_bounds__(128, 4) void qkv_mma_kernel(const float* __restrict__ X)
{
    const int tid  = threadIdx.x;
    const int wid  = tid >> 5;
    const int lane = tid & 31;
    const int gq   = lane >> 2;
    const int tq   = lane & 3;
    const int mat  = blockIdx.y;
    const int zn   = blockIdx.z;
    const int r0   = blockIdx.x * 64 + wid * 16 + gq;
    const int r1   = r0 + 8;

    // A-fragments for all 8 k-steps (hi/lo)
    uint32_t ahi[8][4], alo[8][4];
    {
        const float* x0 = X + (size_t)r0 * EMB;
        const float* x1 = X + (size_t)r1 * EMB;
        #pragma unroll
        for (int ks = 0; ks < 8; ks++) {
            const int k0 = ks * 16;
            float2 v[4];
            v[0] = *(const float2*)(x0 + k0 + 2 * tq);
            v[1] = *(const float2*)(x1 + k0 + 2 * tq);
            v[2] = *(const float2*)(x0 + k0 + 8 + 2 * tq);
            v[3] = *(const float2*)(x1 + k0 + 8 + 2 * tq);
            #pragma unroll
            for (int i = 0; i < 4; i++) {
                const uint32_t hp = bf2(v[i].x, v[i].y);
                ahi[ks][i] = hp;
                alo[ks][i] = bf2(v[i].x - bflo(hp), v[i].y - bfhi(hp));
            }
        }
    }

    const uint16_t* wh = g_Wthi + (size_t)mat * EMB * EMB;
    const uint16_t* wl = g_Wtlo + (size_t)mat * EMB * EMB;

    const int b = r0 >> 11;
    const int s0 = r0 & (SEQ - 1);
    const int s1 = r1 & (SEQ - 1);

    #pragma unroll
    for (int ntl = 0; ntl < 4; ntl++) {
        const int nt = zn * 4 + ntl;
        const int nrow = nt * 8 + gq;
        float acc[4] = {0.f, 0.f, 0.f, 0.f};
        #pragma unroll
        for (int ks = 0; ks < 8; ks++) {
            const size_t base = (size_t)nrow * EMB + ks * 16 + 4 * tq;
            const uint2 bhv = *(const uint2*)&wh[base];
            const uint2 blv = *(const uint2*)&wl[base];
            uint32_t bh2[2] = {bhv.x, bhv.y};
            uint32_t bl2[2] = {blv.x, blv.y};
            mma16816(acc, ahi[ks], bh2);
            mma16816(acc, ahi[ks], bl2);
            mma16816(acc, alo[ks], bh2);
        }
        // epilogue: cols c0 = nt*8 + 2tq, c0+1; rows r0 (acc0,1), r1 (acc2,3)
        const int c0 = nt * 8 + 2 * tq;
        #pragma unroll
        for (int j = 0; j < 2; j++) {
            const int c = c0 + j;
            const int h = c & 7;
            const int d = c >> 3;
            const int bh_ = b * NH + h;
            const float v0 = acc[j];
            const float v1 = acc[2 + j];
            if (mat == 0) {
                g_Q[((size_t)bh_ * SEQ + s0) * HD + d] = v0;
                g_Q[((size_t)bh_ * SEQ + s1) * HD + d] = v1;
            } else if (mat == 1) {
                g_K[((size_t)bh_ * SEQ + s0) * HD + d] = v0;
                g_K[((size_t)bh_ * SEQ + s1) * HD + d] = v1;
            } else {
                g_Vt[((size_t)bh_ * HD + d) * SEQ + s0] = v0;
                g_Vt[((size_t)bh_ * HD + d) * SEQ + s1] = v1;
            }
        }
    }
}

// ---------------------------------------------------------------------------
// Kernel 1b: COMPACTING bf16 hi/lo precompute (unchanged from R15).
// ---------------------------------------------------------------------------
__global__ __launch_bounds__(256) void convert_kernel()
{
    const int u = blockIdx.x * 256 + threadIdx.x;
    float x[16];
    uint16_t *dh, *dl;

    if (u < NROWS * NH) {
        const int bh = u >> 11;
        const int j  = u & (SEQ - 1);
        const int b  = bh >> 3;
        dh = g_Khi + (size_t)u * HD;
        dl = g_Klo + (size_t)u * HD;
        if (j < g_nkeys[b]) {
            const int s = g_cidx[b * SEQ + j];
            const float* src = g_K + ((size_t)bh * SEQ + s) * HD;
            #pragma unroll
            for (int i = 0; i < 4; i++)
                *(float4*)&x[4 * i] = *(const float4*)(src + 4 * i);
        } else {
            #pragma unroll
            for (int i = 0; i < 16; i++) x[i] = 0.f;
        }
    } else {
        const int v = u - NROWS * NH;
        const int row = v >> 7;
        const int j0  = (v & 127) * 16;
        const int b   = row >> 7;
        const size_t off = (size_t)row * SEQ + j0;
        dh = g_Vthi + off;
        dl = g_Vtlo + off;
        const int nk = g_nkeys[b];
        const float* src = g_Vt + (size_t)row * SEQ;
        const int* ci = g_cidx + b * SEQ + j0;
        #pragma unroll
        for (int i = 0; i < 16; i++)
            x[i] = (j0 + i < nk) ? src[ci[i]] : 0.f;
    }

    union { uint16_t u16[16]; uint4 u4[2]; } hh, ll;
    #pragma unroll
    for (int i = 0; i < 16; i++) {
        const uint32_t hb = bfr(x[i]);
        const uint32_t lb = bfr(x[i] - __uint_as_float(hb << 16));
        const int p = permF(i);
        hh.u16[p] = (uint16_t)hb;
        ll.u16[p] = (uint16_t)lb;
    }
    *(uint4*)&dh[0] = hh.u4[0];
    *(uint4*)&dh[8] = hh.u4[1];
    *(uint4*)&dl[0] = ll.u4[0];
    *(uint4*)&dl[8] = ll.u4[1];
}

// ---------------------------------------------------------------------------
// Kernel 2: flash attention over compacted keys (unchanged from R15).
// ---------------------------------------------------------------------------
__global__ __launch_bounds__(128, 4) void attn_kernel()
{
    __shared__ __align__(16) uint16_t sKhi[KTILE * KPAD];
    __shared__ __align__(16) uint16_t sKlo[KTILE * KPAD];
    __shared__ __align__(16) uint16_t sVhi[16 * VPAD];
    __shared__ __align__(16) uint16_t sVlo[16 * VPAD];
    __shared__ float addm[KTILE];

    const int tid  = threadIdx.x;
    const int wid  = tid >> 5;
    const int lane = tid & 31;
    const int gq   = lane >> 2;
    const int tq   = lane & 3;
    const int bh   = blockIdx.y;
    const int b    = bh >> 3;
    const int z    = blockIdx.z;
    const int qb   = blockIdx.x * 64 + wid * 16;
    const int row0 = qb + gq;
    const int row1 = qb + gq + 8;

    const int nkeys  = g_nkeys[b];
    const int ntiles = (nkeys + KTILE - 1) >> 6;
    const int htile  = (ntiles + 1) >> 1;
    const int tbeg   = z ? htile : 0;
    const int tend   = z ? ntiles : htile;

    uint32_t qhi[4], qlo[4];
    {
        const float SC = 0.3606737602222409f;
        const float* q0p = g_Q + ((size_t)bh * SEQ + row0) * HD;
        const float* q1p = g_Q + ((size_t)bh * SEQ + row1) * HD;
        float2 x[4];
        x[0] = *(const float2*)(q0p + 2 * tq);
        x[1] = *(const float2*)(q1p + 2 * tq);
        x[2] = *(const float2*)(q0p + 2 * tq + 8);
        x[3] = *(const float2*)(q1p + 2 * tq + 8);
        #pragma unroll
        for (int i = 0; i < 4; i++) {
            const float e = x[i].x * SC, o = x[i].y * SC;
            const uint32_t hp = bf2(e, o);
            qhi[i] = hp;
            qlo[i] = bf2(e - bflo(hp), o - bfhi(hp));
        }
    }

    float m0 = -1e30f, m1 = -1e30f, l0 = 0.f, l1 = 0.f;
    float ocf[2][4];
    #pragma unroll
    for (int nv = 0; nv < 2; nv++)
        #pragma unroll
        for (int j = 0; j < 4; j++) ocf[nv][j] = 0.f;

    const float NEGM = -1442.6950408889634f;
    const int key = tid >> 1, half = tid & 1;
    const int dv  = tid >> 3, kg   = tid & 7;

    const uint16_t* gKh = g_Khi + (size_t)bh * SEQ * HD;
    const uint16_t* gKl = g_Klo + (size_t)bh * SEQ * HD;
    const uint16_t* gVh = g_Vthi + (size_t)bh * HD * SEQ;
    const uint16_t* gVl = g_Vtlo + (size_t)bh * HD * SEQ;

    for (int t = tbeg; t < tend; t++) {
        const int kb = t * KTILE;
        __syncthreads();
        {
            const size_t src = ((size_t)(kb + key)) * HD + half * 8;
            *(uint4*)&sKhi[key * KPAD + half * 8] = *(const uint4*)&gKh[src];
            *(uint4*)&sKlo[key * KPAD + half * 8] = *(const uint4*)&gKl[src];
        }
        {
            const size_t src = (size_t)dv * SEQ + kb + kg * 8;
            *(uint4*)&sVhi[dv * VPAD + kg * 8] = *(const uint4*)&gVh[src];
            *(uint4*)&sVlo[dv * VPAD + kg * 8] = *(const uint4*)&gVl[src];
        }
        if (tid < KTILE)
            addm[tid] = (kb + tid < nkeys) ? 0.f : NEGM;
        __syncthreads();

        float s[8][4];
        float rm0 = -1e30f, rm1 = -1e30f;
        #pragma unroll
        for (int n = 0; n < 8; n++) {
            const int krow = n * 8 + gq;
            const uint2 kh = *(const uint2*)&sKhi[krow * KPAD + 4 * tq];
            const uint2 kl = *(const uint2*)&sKlo[krow * KPAD + 4 * tq];
            uint32_t kbh[2] = {kh.x, kh.y};
            uint32_t kbl[2] = {kl.x, kl.y};
            float cc[4] = {0.f, 0.f, 0.f, 0.f};
            mma16816(cc, qhi, kbh);
            mma16816(cc, qhi, kbl);
            mma16816(cc, qlo, kbh);
            const float am0 = addm[n * 8 + 2 * tq];
            const float am1 = addm[n * 8 + 2 * tq + 1];
            s[n][0] = cc[0] + am0;  s[n][1] = cc[1] + am1;
            s[n][2] = cc[2] + am0;  s[n][3] = cc[3] + am1;
            rm0 = fmaxf(rm0, fmaxf(s[n][0], s[n][1]));
            rm1 = fmaxf(rm1, fmaxf(s[n][2], s[n][3]));
        }

        rm0 = fmaxf(rm0, __shfl_xor_sync(0xFFFFFFFFu, rm0, 1));
        rm0 = fmaxf(rm0, __shfl_xor_sync(0xFFFFFFFFu, rm0, 2));
        rm1 = fmaxf(rm1, __shfl_xor_sync(0xFFFFFFFFu, rm1, 1));
        rm1 = fmaxf(rm1, __shfl_xor_sync(0xFFFFFFFFu, rm1, 2));
        const float nm0 = fmaxf(m0, rm0);
        const float nm1 = fmaxf(m1, rm1);
        const float c0 = ex2f(m0 - nm0);
        const float c1 = ex2f(m1 - nm1);
        m0 = nm0; m1 = nm1;
        l0 *= c0; l1 *= c1;
        #pragma unroll
        for (int nv = 0; nv < 2; nv++) {
            ocf[nv][0] *= c0;  ocf[nv][1] *= c0;
            ocf[nv][2] *= c1;  ocf[nv][3] *= c1;
        }
        #pragma unroll
        for (int n = 0; n < 8; n++) {
            s[n][0] = ex2f(s[n][0] - m0);
            s[n][1] = ex2f(s[n][1] - m0);
            s[n][2] = ex2f(s[n][2] - m1);
            s[n][3] = ex2f(s[n][3] - m1);
            l0 += s[n][0] + s[n][1];
            l1 += s[n][2] + s[n][3];
        }

        #pragma unroll
        for (int ks = 0; ks < 4; ks++) {
            uint32_t pah[4], pal[4];
            {
                uint32_t hp;
                hp = bf2(s[2*ks][0], s[2*ks][1]);   pah[0] = hp;
                pal[0] = bf2(s[2*ks][0] - bflo(hp), s[2*ks][1] - bfhi(hp));
                hp = bf2(s[2*ks][2], s[2*ks][3]);   pah[1] = hp;
                pal[1] = bf2(s[2*ks][2] - bflo(hp), s[2*ks][3] - bfhi(hp));
                hp = bf2(s[2*ks+1][0], s[2*ks+1][1]); pah[2] = hp;
                pal[2] = bf2(s[2*ks+1][0] - bflo(hp), s[2*ks+1][1] - bfhi(hp));
                hp = bf2(s[2*ks+1][2], s[2*ks+1][3]); pah[3] = hp;
                pal[3] = bf2(s[2*ks+1][2] - bflo(hp), s[2*ks+1][3] - bfhi(hp));
            }
            #pragma unroll
            for (int nv = 0; nv < 2; nv++) {
                const int vrow = nv * 8 + gq;
                const uint2 vh = *(const uint2*)&sVhi[vrow * VPAD + 16 * ks + 4 * tq];
                const uint2 vl = *(const uint2*)&sVlo[vrow * VPAD + 16 * ks + 4 * tq];
                uint32_t vbh[2] = {vh.x, vh.y};
                uint32_t vbl[2] = {vl.x, vl.y};
                mma16816(ocf[nv], pah, vbh);
                mma16816(ocf[nv], pah, vbl);
                mma16816(ocf[nv], pal, vbh);
            }
        }
    }

    l0 += __shfl_xor_sync(0xFFFFFFFFu, l0, 1);
    l0 += __shfl_xor_sync(0xFFFFFFFFu, l0, 2);
    l1 += __shfl_xor_sync(0xFFFFFFFFu, l1, 1);
    l1 += __shfl_xor_sync(0xFFFFFFFFu, l1, 2);

    float* pr0 = g_part + (((size_t)bh * SEQ + row0) * NKV + z) * PREC;
    float* pr1 = g_part + (((size_t)bh * SEQ + row1) * NKV + z) * PREC;
    *(float2*)&pr0[2 * tq]     = make_float2(ocf[0][0], ocf[0][1]);
    *(float2*)&pr0[8 + 2 * tq] = make_float2(ocf[1][0], ocf[1][1]);
    *(float2*)&pr1[2 * tq]     = make_float2(ocf[0][2], ocf[0][3]);
    *(float2*)&pr1[8 + 2 * tq] = make_float2(ocf[1][2], ocf[1][3]);
    if (tq == 0) {
        pr0[16] = m0;  pr0[17] = l0;
        pr1[16] = m1;  pr1[17] = l1;
    }
}

// ---------------------------------------------------------------------------
// Kernel 3: merge NKV partials (unchanged from R14/R15).
// ---------------------------------------------------------------------------
__global__ __launch_bounds__(128) void combine_kernel(float* __restrict__ out)
{
    const int idx = blockIdx.x * 128 + threadIdx.x;
    const int c = idx & 3;
    const int h = (idx >> 2) & 7;
    const int r = idx >> 5;
    const float* p = g_part + (((size_t)((r >> 11) * NH + h) * SEQ + (r & (SEQ - 1))) * NKV) * PREC;

    const float mm0 = p[16], ll0 = p[17];
    const float mm1 = p[PREC + 16], ll1 = p[PREC + 17];
    const float M = fmaxf(mm0, mm1);
    const float w0 = ex2f(mm0 - M), w1 = ex2f(mm1 - M);
    const float inv = 1.f / (ll0 * w0 + ll1 * w1);

    const float4 a0 = *(const float4*)(p + 4 * c);
    const float4 a1 = *(const float4*)(p + PREC + 4 * c);

    float* op = out + (size_t)r * EMB + h;
    op[(4*c+0) * NH] = (a0.x * w0 + a1.x * w1) * inv;
    op[(4*c+1) * NH] = (a0.y * w0 + a1.y * w1) * inv;
    op[(4*c+2) * NH] = (a0.z * w0 + a1.z * w1) * inv;
    op[(4*c+3) * NH] = (a0.w * w0 + a1.w * w1) * inv;
}

extern "C" void kernel_launch(void* const* d_in, const int* in_sizes, int n_in,
                              void* d_out, int out_size)
{
    const float* X    = (const float*)d_in[0];
    const int*   msk  = (const int*)d_in[1];
    // d_in[2] = target mask (unused, encoder path), d_in[3] = masked flag (0)
    const float* Wq   = (const float*)d_in[4];
    const float* Wk   = (const float*)d_in[5];
    const float* Wv   = (const float*)d_in[6];
    float* out        = (float*)d_out;

    wconv_kernel<<<12, 256>>>(Wq, Wk, Wv);
    mask_scan_kernel<<<BATCH, 256>>>(msk);

    dim3 pgrid(NROWS / 64, 3, 4);
    qkv_mma_kernel<<<pgrid, 128>>>(X);

    convert_kernel<<<256, 256>>>();

    dim3 agrid(SEQ / 64, BATCH * NH, NKV);
    attn_kernel<<<agrid, 128>>>();

    combine_kernel<<<BATCH * NH * SEQ * 4 / 128, 128>>>(out);
}

// round 17
// speedup vs baseline: 1.0339x; 1.0339x over previous
#include <cuda_runtime.h>
#include <cstdint>

#define BATCH 2
#define SEQ   2048
#define EMB   128
#define NH    8
#define HD    16
#define NROWS (BATCH*SEQ)
#define KTILE 64
#define NKV   2
#define PREC  20
#define KPAD  16     // uint16 per K smem row (32B)
#define VPAD  80     // uint16 per V^t smem row (160B)

// Scratch
__device__ float g_Q[BATCH*NH*SEQ*HD];
__device__ float g_K[BATCH*NH*SEQ*HD];
__device__ float g_Vt[BATCH*NH*HD*SEQ];
// Compacted (masked keys removed) bf16 hi/lo, fragment-permuted
__device__ __align__(16) uint16_t g_Khi[BATCH*NH*SEQ*HD];
__device__ __align__(16) uint16_t g_Klo[BATCH*NH*SEQ*HD];
__device__ __align__(16) uint16_t g_Vthi[BATCH*NH*HD*SEQ];
__device__ __align__(16) uint16_t g_Vtlo[BATCH*NH*HD*SEQ];
// Mask compaction
__device__ int g_cidx[BATCH*SEQ];
__device__ int g_nkeys[BATCH];
// Partials: [bh][q][z][PREC]
__device__ float g_part[BATCH*NH*SEQ*NKV*PREC];

__device__ __forceinline__ float ex2f(float x){
    float y; asm("ex2.approx.ftz.f32 %0, %1;" : "=f"(y) : "f"(x)); return y;
}
__device__ __forceinline__ uint32_t bf2(float even, float odd){
    uint32_t r;
    asm("cvt.rn.bf16x2.f32 %0, %1, %2;" : "=r"(r) : "f"(odd), "f"(even));
    return r;
}
__device__ __forceinline__ float bflo(uint32_t r){ return __uint_as_float(r << 16); }
__device__ __forceinline__ float bfhi(uint32_t r){ return __uint_as_float(r & 0xFFFF0000u); }
__device__ __forceinline__ uint32_t bfr(float x){ return bf2(x, 0.f) & 0xFFFFu; }

// fragment permutation within a 16-element block (verified R10-R16)
__device__ __forceinline__ int permF(int i){
    return (i < 8) ? (4 * (i >> 1) + (i & 1))
                   : (4 * ((i - 8) >> 1) + 2 + (i & 1));
}

__device__ __forceinline__ void mma16816(float c[4], const uint32_t a[4], const uint32_t b[2]){
    asm volatile(
        "mma.sync.aligned.m16n8k16.row.col.f32.bf16.bf16.f32 "
        "{%0,%1,%2,%3}, {%4,%5,%6,%7}, {%8,%9}, {%0,%1,%2,%3};\n"
        : "+f"(c[0]), "+f"(c[1]), "+f"(c[2]), "+f"(c[3])
        : "r"(a[0]), "r"(a[1]), "r"(a[2]), "r"(a[3]), "r"(b[0]), "r"(b[1]));
}

// ---------------------------------------------------------------------------
// Kernel 0: mask compaction (R15 proven).
// ---------------------------------------------------------------------------
__global__ __launch_bounds__(256) void mask_scan_kernel(const int* __restrict__ mask)
{
    __shared__ int warpsum[8];
    const int b = blockIdx.x;
    const int tid = threadIdx.x;
    const int lane = tid & 31, w = tid >> 5;

    int flags[8], cnt = 0;
    #pragma unroll
    for (int i = 0; i < 8; i++) {
        flags[i] = (mask[b * SEQ + tid * 8 + i] != 0);
        cnt += flags[i];
    }
    int scan = cnt;
    #pragma unroll
    for (int off = 1; off < 32; off <<= 1) {
        const int n = __shfl_up_sync(0xFFFFFFFFu, scan, off);
        if (lane >= off) scan += n;
    }
    if (lane == 31) warpsum[w] = scan;
    __syncthreads();
    int wbase = 0;
    #pragma unroll
    for (int i = 0; i < 8; i++)
        if (i < w) wbase += warpsum[i];
    int pos = wbase + scan - cnt;
    #pragma unroll
    for (int i = 0; i < 8; i++) {
        if (flags[i]) g_cidx[b * SEQ + pos++] = tid * 8 + i;
    }
    if (tid == 255) g_nkeys[b] = wbase + scan;
}

// ---------------------------------------------------------------------------
// Kernel 1: QKV projection + head split (R8/R15 proven scalar form).
// ---------------------------------------------------------------------------
__global__ __launch_bounds__(256) void qkv_kernel(
    const float* __restrict__ X,
    const float* __restrict__ Wq, const float* __restrict__ Wk,
    const float* __restrict__ Wv)
{
    __shared__ __align__(16) float Xs[32][EMB];
    const int tid = threadIdx.x;
    const int r0 = blockIdx.x * 32;
    const int mat = blockIdx.y;
    const float* __restrict__ W = (mat == 0) ? Wq : (mat == 1) ? Wk : Wv;

    {
        const float4* xg = (const float4*)(X + (size_t)r0 * EMB);
        float4* xs = (float4*)&Xs[0][0];
        #pragma unroll
        for (int i = 0; i < 4; i++)
            xs[tid + 256 * i] = xg[tid + 256 * i];
    }
    __syncthreads();

    const int oc = tid & 31;
    const int c4 = oc * 4;
    const int rg = tid >> 5;

    float a[4][4];
    #pragma unroll
    for (int i = 0; i < 4; i++)
        #pragma unroll
        for (int j = 0; j < 4; j++) a[i][j] = 0.f;

    #pragma unroll 2
    for (int e0 = 0; e0 < EMB; e0 += 4) {
        float4 xr[4];
        #pragma unroll
        for (int i = 0; i < 4; i++)
            xr[i] = *(const float4*)&Xs[rg * 4 + i][e0];
        #pragma unroll
        for (int ee = 0; ee < 4; ee++) {
            const float4 w = *(const float4*)(W + (e0 + ee) * EMB + c4);
            #pragma unroll
            for (int i = 0; i < 4; i++) {
                const float x = (ee == 0) ? xr[i].x : (ee == 1) ? xr[i].y
                              : (ee == 2) ? xr[i].z : xr[i].w;
                a[i][0] += x * w.x;
                a[i][1] += x * w.y;
                a[i][2] += x * w.z;
                a[i][3] += x * w.w;
            }
        }
    }

    #pragma unroll
    for (int i = 0; i < 4; i++) {
        const int r = r0 + rg * 4 + i;
        const int b = r >> 11;
        const int s = r & (SEQ - 1);
        #pragma unroll
        for (int j = 0; j < 4; j++) {
            const int c = c4 + j;
            const int h = c & 7;
            const int d = c >> 3;
            const int bh = b * NH + h;
            if (mat == 0)
                g_Q[((size_t)bh * SEQ + s) * HD + d] = a[i][j];
            else if (mat == 1)
                g_K[((size_t)bh * SEQ + s) * HD + d] = a[i][j];
            else
                g_Vt[((size_t)bh * HD + d) * SEQ + s] = a[i][j];
        }
    }
}

// ---------------------------------------------------------------------------
// Kernel 1b: COMPACTING bf16 hi/lo precompute. 128-thread blocks (512 CTAs,
// 2x residency vs R15) and V^t indices preloaded as int4 so all 16 data
// gathers are independent (MLP ~16 instead of serial).
// ---------------------------------------------------------------------------
__global__ __launch_bounds__(128) void convert_kernel()
{
    const int u = blockIdx.x * 128 + threadIdx.x;
    float x[16];
    uint16_t *dh, *dl;

    if (u < NROWS * NH) {                 // compacted K rows
        const int bh = u >> 11;
        const int j  = u & (SEQ - 1);
        const int b  = bh >> 3;
        dh = g_Khi + (size_t)u * HD;
        dl = g_Klo + (size_t)u * HD;
        if (j < g_nkeys[b]) {
            const int s = g_cidx[b * SEQ + j];
            const float* src = g_K + ((size_t)bh * SEQ + s) * HD;
            #pragma unroll
            for (int i = 0; i < 4; i++)
                *(float4*)&x[4 * i] = *(const float4*)(src + 4 * i);
        } else {
            #pragma unroll
            for (int i = 0; i < 16; i++) x[i] = 0.f;
        }
    } else {                              // compacted V^t segments
        const int v = u - NROWS * NH;
        const int row = v >> 7;           // bh*HD + d
        const int j0  = (v & 127) * 16;
        const int b   = row >> 7;
        const size_t off = (size_t)row * SEQ + j0;
        dh = g_Vthi + off;
        dl = g_Vtlo + off;
        const int nk = g_nkeys[b];
        const float* src = g_Vt + (size_t)row * SEQ;
        // preload all 16 indices as 4x int4 (64B coalesced), then gather
        int4 ci[4];
        #pragma unroll
        for (int i = 0; i < 4; i++)
            ci[i] = *(const int4*)(g_cidx + b * SEQ + j0 + 4 * i);
        const int idxs[16] = {ci[0].x, ci[0].y, ci[0].z, ci[0].w,
                              ci[1].x, ci[1].y, ci[1].z, ci[1].w,
                              ci[2].x, ci[2].y, ci[2].z, ci[2].w,
                              ci[3].x, ci[3].y, ci[3].z, ci[3].w};
        #pragma unroll
        for (int i = 0; i < 16; i++)
            x[i] = (j0 + i < nk) ? src[idxs[i]] : 0.f;
    }

    union { uint16_t u16[16]; uint4 u4[2]; } hh, ll;
    #pragma unroll
    for (int i = 0; i < 16; i++) {
        const uint32_t hb = bfr(x[i]);
        const uint32_t lb = bfr(x[i] - __uint_as_float(hb << 16));
        const int p = permF(i);
        hh.u16[p] = (uint16_t)hb;
        ll.u16[p] = (uint16_t)lb;
    }
    *(uint4*)&dh[0] = hh.u4[0];
    *(uint4*)&dh[8] = hh.u4[1];
    *(uint4*)&dl[0] = ll.u4[0];
    *(uint4*)&dl[8] = ll.u4[1];
}

// ---------------------------------------------------------------------------
// Kernel 2: flash attention over compacted keys (R15 proven, unchanged).
// ---------------------------------------------------------------------------
__global__ __launch_bounds__(128, 4) void attn_kernel()
{
    __shared__ __align__(16) uint16_t sKhi[KTILE * KPAD];
    __shared__ __align__(16) uint16_t sKlo[KTILE * KPAD];
    __shared__ __align__(16) uint16_t sVhi[16 * VPAD];
    __shared__ __align__(16) uint16_t sVlo[16 * VPAD];
    __shared__ float addm[KTILE];

    const int tid  = threadIdx.x;
    const int wid  = tid >> 5;
    const int lane = tid & 31;
    const int gq   = lane >> 2;
    const int tq   = lane & 3;
    const int bh   = blockIdx.y;
    const int b    = bh >> 3;
    const int z    = blockIdx.z;
    const int qb   = blockIdx.x * 64 + wid * 16;
    const int row0 = qb + gq;
    const int row1 = qb + gq + 8;

    const int nkeys  = g_nkeys[b];
    const int ntiles = (nkeys + KTILE - 1) >> 6;
    const int htile  = (ntiles + 1) >> 1;
    const int tbeg   = z ? htile : 0;
    const int tend   = z ? ntiles : htile;

    uint32_t qhi[4], qlo[4];
    {
        const float SC = 0.3606737602222409f;
        const float* q0p = g_Q + ((size_t)bh * SEQ + row0) * HD;
        const float* q1p = g_Q + ((size_t)bh * SEQ + row1) * HD;
        float2 x[4];
        x[0] = *(const float2*)(q0p + 2 * tq);
        x[1] = *(const float2*)(q1p + 2 * tq);
        x[2] = *(const float2*)(q0p + 2 * tq + 8);
        x[3] = *(const float2*)(q1p + 2 * tq + 8);
        #pragma unroll
        for (int i = 0; i < 4; i++) {
            const float e = x[i].x * SC, o = x[i].y * SC;
            const uint32_t hp = bf2(e, o);
            qhi[i] = hp;
            qlo[i] = bf2(e - bflo(hp), o - bfhi(hp));
        }
    }

    float m0 = -1e30f, m1 = -1e30f, l0 = 0.f, l1 = 0.f;
    float ocf[2][4];
    #pragma unroll
    for (int nv = 0; nv < 2; nv++)
        #pragma unroll
        for (int j = 0; j < 4; j++) ocf[nv][j] = 0.f;

    const float NEGM = -1442.6950408889634f;
    const int key = tid >> 1, half = tid & 1;
    const int dv  = tid >> 3, kg   = tid & 7;

    const uint16_t* gKh = g_Khi + (size_t)bh * SEQ * HD;
    const uint16_t* gKl = g_Klo + (size_t)bh * SEQ * HD;
    const uint16_t* gVh = g_Vthi + (size_t)bh * HD * SEQ;
    const uint16_t* gVl = g_Vtlo + (size_t)bh * HD * SEQ;

    for (int t = tbeg; t < tend; t++) {
        const int kb = t * KTILE;
        __syncthreads();
        {
            const size_t src = ((size_t)(kb + key)) * HD + half * 8;
            *(uint4*)&sKhi[key * KPAD + half * 8] = *(const uint4*)&gKh[src];
            *(uint4*)&sKlo[key * KPAD + half * 8] = *(const uint4*)&gKl[src];
        }
        {
            const size_t src = (size_t)dv * SEQ + kb + kg * 8;
            *(uint4*)&sVhi[dv * VPAD + kg * 8] = *(const uint4*)&gVh[src];
            *(uint4*)&sVlo[dv * VPAD + kg * 8] = *(const uint4*)&gVl[src];
        }
        if (tid < KTILE)
            addm[tid] = (kb + tid < nkeys) ? 0.f : NEGM;
        __syncthreads();

        float s[8][4];
        float rm0 = -1e30f, rm1 = -1e30f;
        #pragma unroll
        for (int n = 0; n < 8; n++) {
            const int krow = n * 8 + gq;
            const uint2 kh = *(const uint2*)&sKhi[krow * KPAD + 4 * tq];
            const uint2 kl = *(const uint2*)&sKlo[krow * KPAD + 4 * tq];
            uint32_t kbh[2] = {kh.x, kh.y};
            uint32_t kbl[2] = {kl.x, kl.y};
            float cc[4] = {0.f, 0.f, 0.f, 0.f};
            mma16816(cc, qhi, kbh);
            mma16816(cc, qhi, kbl);
            mma16816(cc, qlo, kbh);
            const float am0 = addm[n * 8 + 2 * tq];
            const float am1 = addm[n * 8 + 2 * tq + 1];
            s[n][0] = cc[0] + am0;  s[n][1] = cc[1] + am1;
            s[n][2] = cc[2] + am0;  s[n][3] = cc[3] + am1;
            rm0 = fmaxf(rm0, fmaxf(s[n][0], s[n][1]));
            rm1 = fmaxf(rm1, fmaxf(s[n][2], s[n][3]));
        }

        rm0 = fmaxf(rm0, __shfl_xor_sync(0xFFFFFFFFu, rm0, 1));
        rm0 = fmaxf(rm0, __shfl_xor_sync(0xFFFFFFFFu, rm0, 2));
        rm1 = fmaxf(rm1, __shfl_xor_sync(0xFFFFFFFFu, rm1, 1));
        rm1 = fmaxf(rm1, __shfl_xor_sync(0xFFFFFFFFu, rm1, 2));
        const float nm0 = fmaxf(m0, rm0);
        const float nm1 = fmaxf(m1, rm1);
        const float c0 = ex2f(m0 - nm0);
        const float c1 = ex2f(m1 - nm1);
        m0 = nm0; m1 = nm1;
        l0 *= c0; l1 *= c1;
        #pragma unroll
        for (int nv = 0; nv < 2; nv++) {
            ocf[nv][0] *= c0;  ocf[nv][1] *= c0;
            ocf[nv][2] *= c1;  ocf[nv][3] *= c1;
        }
        #pragma unroll
        for (int n = 0; n < 8; n++) {
            s[n][0] = ex2f(s[n][0] - m0);
            s[n][1] = ex2f(s[n][1] - m0);
            s[n][2] = ex2f(s[n][2] - m1);
            s[n][3] = ex2f(s[n][3] - m1);
            l0 += s[n][0] + s[n][1];
            l1 += s[n][2] + s[n][3];
        }

        #pragma unroll
        for (int ks = 0; ks < 4; ks++) {
            uint32_t pah[4], pal[4];
            {
                uint32_t hp;
                hp = bf2(s[2*ks][0], s[2*ks][1]);   pah[0] = hp;
                pal[0] = bf2(s[2*ks][0] - bflo(hp), s[2*ks][1] - bfhi(hp));
                hp = bf2(s[2*ks][2], s[2*ks][3]);   pah[1] = hp;
                pal[1] = bf2(s[2*ks][2] - bflo(hp), s[2*ks][3] - bfhi(hp));
                hp = bf2(s[2*ks+1][0], s[2*ks+1][1]); pah[2] = hp;
                pal[2] = bf2(s[2*ks+1][0] - bflo(hp), s[2*ks+1][1] - bfhi(hp));
                hp = bf2(s[2*ks+1][2], s[2*ks+1][3]); pah[3] = hp;
                pal[3] = bf2(s[2*ks+1][2] - bflo(hp), s[2*ks+1][3] - bfhi(hp));
            }
            #pragma unroll
            for (int nv = 0; nv < 2; nv++) {
                const int vrow = nv * 8 + gq;
                const uint2 vh = *(const uint2*)&sVhi[vrow * VPAD + 16 * ks + 4 * tq];
                const uint2 vl = *(const uint2*)&sVlo[vrow * VPAD + 16 * ks + 4 * tq];
                uint32_t vbh[2] = {vh.x, vh.y};
                uint32_t vbl[2] = {vl.x, vl.y};
                mma16816(ocf[nv], pah, vbh);
                mma16816(ocf[nv], pah, vbl);
                mma16816(ocf[nv], pal, vbh);
            }
        }
    }

    l0 += __shfl_xor_sync(0xFFFFFFFFu, l0, 1);
    l0 += __shfl_xor_sync(0xFFFFFFFFu, l0, 2);
    l1 += __shfl_xor_sync(0xFFFFFFFFu, l1, 1);
    l1 += __shfl_xor_sync(0xFFFFFFFFu, l1, 2);

    float* pr0 = g_part + (((size_t)bh * SEQ + row0) * NKV + z) * PREC;
    float* pr1 = g_part + (((size_t)bh * SEQ + row1) * NKV + z) * PREC;
    *(float2*)&pr0[2 * tq]     = make_float2(ocf[0][0], ocf[0][1]);
    *(float2*)&pr0[8 + 2 * tq] = make_float2(ocf[1][0], ocf[1][1]);
    *(float2*)&pr1[2 * tq]     = make_float2(ocf[0][2], ocf[0][3]);
    *(float2*)&pr1[8 + 2 * tq] = make_float2(ocf[1][2], ocf[1][3]);
    if (tq == 0) {
        pr0[16] = m0;  pr0[17] = l0;
        pr1[16] = m1;  pr1[17] = l1;
    }
}

// ---------------------------------------------------------------------------
// Kernel 3: merge NKV partials (R14/R15 proven, unchanged).
// ---------------------------------------------------------------------------
__global__ __launch_bounds__(128) void combine_kernel(float* __restrict__ out)
{
    const int idx = blockIdx.x * 128 + threadIdx.x;
    const int c = idx & 3;
    const int h = (idx >> 2) & 7;
    const int r = idx >> 5;
    const float* p = g_part + (((size_t)((r >> 11) * NH + h) * SEQ + (r & (SEQ - 1))) * NKV) * PREC;

    const float mm0 = p[16], ll0 = p[17];
    const float mm1 = p[PREC + 16], ll1 = p[PREC + 17];
    const float M = fmaxf(mm0, mm1);
    const float w0 = ex2f(mm0 - M), w1 = ex2f(mm1 - M);
    const float inv = 1.f / (ll0 * w0 + ll1 * w1);

    const float4 a0 = *(const float4*)(p + 4 * c);
    const float4 a1 = *(const float4*)(p + PREC + 4 * c);

    float* op = out + (size_t)r * EMB + h;
    op[(4*c+0) * NH] = (a0.x * w0 + a1.x * w1) * inv;
    op[(4*c+1) * NH] = (a0.y * w0 + a1.y * w1) * inv;
    op[(4*c+2) * NH] = (a0.z * w0 + a1.z * w1) * inv;
    op[(4*c+3) * NH] = (a0.w * w0 + a1.w * w1) * inv;
}

extern "C" void kernel_launch(void* const* d_in, const int* in_sizes, int n_in,
                              void* d_out, int out_size)
{
    const float* X    = (const float*)d_in[0];
    const int*   msk  = (const int*)d_in[1];
    // d_in[2] = target mask (unused, encoder path), d_in[3] = masked flag (0)
    const float* Wq   = (const float*)d_in[4];
    const float* Wk   = (const float*)d_in[5];
    const float* Wv   = (const float*)d_in[6];
    float* out        = (float*)d_out;

    mask_scan_kernel<<<BATCH, 256>>>(msk);

    dim3 qgrid(NROWS / 32, 3);
    qkv_kernel<<<qgrid, 256>>>(X, Wq, Wk, Wv);

    convert_kernel<<<512, 128>>>();

    dim3 agrid(SEQ / 64, BATCH * NH, NKV);
    attn_kernel<<<agrid, 128>>>();

    combine_kernel<<<BATCH * NH * SEQ * 4 / 128, 128>>>(out);
}